// round 6
// baseline (speedup 1.0000x reference)
#include <cuda_runtime.h>
#include <math.h>
#include <string.h>

#define B_ 512
#define T_ 512
#define I_ 256
#define H_ 250

// ---------------------------------------------------------------------------
// packed fp32x2 helpers
// ---------------------------------------------------------------------------
__device__ __forceinline__ unsigned long long fma2(unsigned long long a,
                                                   unsigned long long b,
                                                   unsigned long long c) {
    unsigned long long d;
    asm("fma.rn.f32x2 %0, %1, %2, %3;" : "=l"(d) : "l"(a), "l"(b), "l"(c));
    return d;
}
__device__ __forceinline__ float2 u2f2(unsigned long long u) {
    float2 f; memcpy(&f, &u, 8); return f;
}
__device__ __forceinline__ unsigned long long f2u2(float x, float y) {
    unsigned long long u;
    asm("mov.b64 %0, {%1, %2};" : "=l"(u) : "f"(x), "f"(y));
    return u;
}

// ---------------------------------------------------------------------------
// Kernel 1: xproj GEMM  out[m, n] = sum_k x[m,k] * Wx[n,k] + bh[n]
//   (unchanged from round 4 — isolate the recurrence change)
// ---------------------------------------------------------------------------
#define BM 128
#define BN 64
#define BK 32
#define TSTRA 36

__global__ __launch_bounds__(256, 2) void xproj_kernel(
    const float* __restrict__ x, const float* __restrict__ Wx,
    const float* __restrict__ bh, float* __restrict__ out)
{
    __shared__ float As[BM][TSTRA];
    __shared__ float Bs[BN][TSTRA];

    const int m0  = blockIdx.x * BM;
    const int n0  = blockIdx.y * BN;
    const int tid = threadIdx.x;
    const int tn  = tid & 15;
    const int tm  = tid >> 4;

    unsigned long long acc[8][4];
#pragma unroll
    for (int i = 0; i < 8; i++)
#pragma unroll
        for (int j = 0; j < 4; j++) acc[i][j] = 0ull;

    const int ar = tid >> 3;
    const int ac = (tid & 7) * 4;

    for (int k0 = 0; k0 < I_; k0 += BK) {
#pragma unroll
        for (int p = 0; p < 4; p++) {
            int row = p * 32 + ar;
            float4 v = *(const float4*)(x + (size_t)(m0 + row) * I_ + k0 + ac);
            *(float4*)&As[row][ac] = v;
        }
#pragma unroll
        for (int p = 0; p < 2; p++) {
            int row = p * 32 + ar;
            int n = n0 + row;
            float4 v = make_float4(0.f, 0.f, 0.f, 0.f);
            if (n < H_) v = *(const float4*)(Wx + (size_t)n * I_ + k0 + ac);
            *(float4*)&Bs[row][ac] = v;
        }
        __syncthreads();

#pragma unroll
        for (int j = 0; j < BK / 4; j++) {
            ulonglong2 b[4];
#pragma unroll
            for (int nn = 0; nn < 4; nn++)
                b[nn] = *(const ulonglong2*)&Bs[tn * 4 + nn][4 * j];
#pragma unroll
            for (int mm = 0; mm < 8; mm++) {
                ulonglong2 a = *(const ulonglong2*)&As[tm * 8 + mm][4 * j];
#pragma unroll
                for (int nn = 0; nn < 4; nn++) {
                    acc[mm][nn] = fma2(a.x, b[nn].x, acc[mm][nn]);
                    acc[mm][nn] = fma2(a.y, b[nn].y, acc[mm][nn]);
                }
            }
        }
        __syncthreads();
    }

#pragma unroll
    for (int nn = 0; nn < 4; nn++) {
        int n = n0 + tn * 4 + nn;
        if (n >= H_) continue;
        float bias = bh[n];
#pragma unroll
        for (int mm = 0; mm < 8; mm++) {
            int m = m0 + tm * 8 + mm;
            float2 f = u2f2(acc[mm][nn]);
            out[(size_t)m * H_ + n] = f.x + f.y + bias;
        }
    }
}

// ---------------------------------------------------------------------------
// Kernel 2: recurrence, batch-in-lane mapping, 512 threads, no cluster.
//   CTA = 4 batches. lane = (slot, batch): slot = lane>>2 within warp,
//   16 warps x 8 slots = 128 slots; slot s (< 125) owns rows s and s+125,
//   one batch, full k. Each (row,batch) pair lives in exactly one lane:
//   finalize (tanh + store) is lane-local, no exchange.
//   Weights k<220 in smem (row stride 220 floats = 55 granules, odd ->
//   1-phase LDS.128 across the 8 distinct rows of a warp); k in [220,250)
//   in registers (2 rows x 15 f32x2 pairs per lane).
//   hp double-buffered -> ONE __syncthreads per step.
// ---------------------------------------------------------------------------
#define RESK  220
#define WST   220          // weight row stride (floats)
#define NREG  15
#define HPST  252          // hp row stride (floats), 63 granules (odd)
#define BT    4

__global__ __launch_bounds__(512, 1) void rnn_rec3(
    const float* __restrict__ h0, const float* __restrict__ Wh,
    float* __restrict__ out)
{
    extern __shared__ float sm[];
    float* Wsm = sm;                       // 250 * 220 floats
    float* hpb = sm + H_ * WST;            // 2 * 4 * 252 floats (double buffer)

    const int tid  = threadIdx.x;
    const int b0   = blockIdx.x * BT;
    const int wid  = tid >> 5;
    const int lane = tid & 31;
    const int slot = wid * 8 + (lane >> 2);   // 0..127
    const int bat  = lane & 3;
    const bool act = (slot < 125);
    const int rowA = slot;
    const int rowB = slot + 125;

    // one-time: weights k<220 into smem (linear copy, coalesced)
    for (int idx = tid; idx < H_ * RESK; idx += 512) {
        int r = idx / RESK;
        int c = idx - r * RESK;
        Wsm[idx] = Wh[(size_t)r * H_ + c];
    }
    // register tail weights k in [220,250) for both rows
    unsigned long long wrA[NREG], wrB[NREG];
    if (act) {
#pragma unroll
        for (int i = 0; i < NREG; i++) {
            float2 ga = *(const float2*)(Wh + (size_t)rowA * H_ + RESK + 2 * i);
            float2 gb = *(const float2*)(Wh + (size_t)rowB * H_ + RESK + 2 * i);
            wrA[i] = f2u2(ga.x, ga.y);
            wrB[i] = f2u2(gb.x, gb.y);
        }
    }
    // hp buffer 0 init from h0 (pads never read: smem j covers k<220,
    // reg part covers k 220..249)
    for (int idx = tid; idx < BT * HPST; idx += 512) {
        int b = idx / HPST;
        int k = idx - b * HPST;
        hpb[idx] = (k < H_) ? h0[(size_t)(b0 + b) * H_ + k] : 0.f;
    }
    __syncthreads();

    const float* wA = Wsm + rowA * WST;
    const float* wB = Wsm + rowB * WST;

    for (int t = 0; t < T_; t++) {
        const float* hpc = hpb + (t & 1) * (BT * HPST) + bat * HPST;
        float*       hpn = hpb + ((t + 1) & 1) * (BT * HPST) + bat * HPST;

        // prefetch xproj values (hide LDG latency under the dots)
        size_t oA = ((size_t)(b0 + bat) * T_ + t) * H_ + rowA;
        size_t oB = ((size_t)(b0 + bat) * T_ + t) * H_ + rowB;
        float xpA = 0.f, xpB = 0.f;
        if (act) { xpA = out[oA]; xpB = out[oB]; }

        unsigned long long aA0 = 0, aA1 = 0, aB0 = 0, aB1 = 0;
        if (act) {
#pragma unroll 5
            for (int j = 0; j < RESK / 4; j++) {       // 55 blocks of 4 k
                ulonglong2 p  = *(const ulonglong2*)(hpc + 4 * j);
                ulonglong2 a  = *(const ulonglong2*)(wA + 4 * j);
                ulonglong2 b  = *(const ulonglong2*)(wB + 4 * j);
                aA0 = fma2(a.x, p.x, aA0);
                aA1 = fma2(a.y, p.y, aA1);
                aB0 = fma2(b.x, p.x, aB0);
                aB1 = fma2(b.y, p.y, aB1);
            }
#pragma unroll
            for (int i = 0; i < NREG; i++) {           // k = 220 .. 249
                unsigned long long p =
                    *(const unsigned long long*)(hpc + RESK + 2 * i);
                aA0 = fma2(wrA[i], p, aA0);
                aB0 = fma2(wrB[i], p, aB0);
            }
        }

        if (act) {
            float2 fa0 = u2f2(aA0), fa1 = u2f2(aA1);
            float2 fb0 = u2f2(aB0), fb1 = u2f2(aB1);
            float vA = tanhf(xpA + (fa0.x + fa0.y) + (fa1.x + fa1.y));
            float vB = tanhf(xpB + (fb0.x + fb0.y) + (fb1.x + fb1.y));
            out[oA] = vA;
            out[oB] = vB;
            hpn[rowA] = vA;       // writes go to the OTHER buffer: no race
            hpn[rowB] = vB;       // with this step's reads
        }
        __syncthreads();          // one barrier/step: writes visible before
                                  // next step's reads of that buffer
    }
}

// ---------------------------------------------------------------------------
extern "C" void kernel_launch(void* const* d_in, const int* in_sizes, int n_in,
                              void* d_out, int out_size)
{
    const float* x  = (const float*)d_in[0];
    const float* h0 = (const float*)d_in[1];
    const float* Wx = (const float*)d_in[2];
    const float* Wh = (const float*)d_in[3];
    const float* bh = (const float*)d_in[4];
    float* out = (float*)d_out;

    static int attr_done = 0;
    size_t smem2 = (size_t)(H_ * WST + 2 * BT * HPST) * sizeof(float);
    if (!attr_done) {
        cudaFuncSetAttribute(rnn_rec3,
                             cudaFuncAttributeMaxDynamicSharedMemorySize,
                             (int)smem2);
        attr_done = 1;
    }

    // 1) xproj + bias into d_out (scratch reuse, no allocation)
    dim3 g1((B_ * T_) / BM, (H_ + BN - 1) / BN);
    xproj_kernel<<<g1, 256>>>(x, Wx, bh, out);

    // 2) recurrence, in-place on d_out: 128 CTAs x 512 threads
    rnn_rec3<<<B_ / BT, 512, smem2>>>(h0, Wh, out);
}

// round 11
// speedup vs baseline: 1.2437x; 1.2437x over previous
#include <cuda_runtime.h>
#include <math.h>
#include <string.h>

#define B_ 512
#define T_ 512
#define I_ 256
#define H_ 250

// ---------------------------------------------------------------------------
// packed fp32x2 helpers
// ---------------------------------------------------------------------------
__device__ __forceinline__ unsigned long long fma2(unsigned long long a,
                                                   unsigned long long b,
                                                   unsigned long long c) {
    unsigned long long d;
    asm("fma.rn.f32x2 %0, %1, %2, %3;" : "=l"(d) : "l"(a), "l"(b), "l"(c));
    return d;
}
__device__ __forceinline__ unsigned long long add2(unsigned long long a,
                                                   unsigned long long b) {
    unsigned long long d;
    asm("add.rn.f32x2 %0, %1, %2;" : "=l"(d) : "l"(a), "l"(b));
    return d;
}
__device__ __forceinline__ float2 u2f2(unsigned long long u) {
    float2 f; memcpy(&f, &u, 8); return f;
}
__device__ __forceinline__ unsigned long long f2u2(float x, float y) {
    unsigned long long u;
    asm("mov.b64 %0, {%1, %2};" : "=l"(u) : "f"(x), "f"(y));
    return u;
}

// ---------------------------------------------------------------------------
// Kernel 1: xproj GEMM  out[m, n] = sum_k x[m,k] * Wx[n,k] + bh[n]
//   (unchanged — isolate the recurrence change)
// ---------------------------------------------------------------------------
#define BM 128
#define BN 64
#define BK 32
#define TSTRA 36

__global__ __launch_bounds__(256, 2) void xproj_kernel(
    const float* __restrict__ x, const float* __restrict__ Wx,
    const float* __restrict__ bh, float* __restrict__ out)
{
    __shared__ float As[BM][TSTRA];
    __shared__ float Bs[BN][TSTRA];

    const int m0  = blockIdx.x * BM;
    const int n0  = blockIdx.y * BN;
    const int tid = threadIdx.x;
    const int tn  = tid & 15;
    const int tm  = tid >> 4;

    unsigned long long acc[8][4];
#pragma unroll
    for (int i = 0; i < 8; i++)
#pragma unroll
        for (int j = 0; j < 4; j++) acc[i][j] = 0ull;

    const int ar = tid >> 3;
    const int ac = (tid & 7) * 4;

    for (int k0 = 0; k0 < I_; k0 += BK) {
#pragma unroll
        for (int p = 0; p < 4; p++) {
            int row = p * 32 + ar;
            float4 v = *(const float4*)(x + (size_t)(m0 + row) * I_ + k0 + ac);
            *(float4*)&As[row][ac] = v;
        }
#pragma unroll
        for (int p = 0; p < 2; p++) {
            int row = p * 32 + ar;
            int n = n0 + row;
            float4 v = make_float4(0.f, 0.f, 0.f, 0.f);
            if (n < H_) v = *(const float4*)(Wx + (size_t)n * I_ + k0 + ac);
            *(float4*)&Bs[row][ac] = v;
        }
        __syncthreads();

#pragma unroll
        for (int j = 0; j < BK / 4; j++) {
            ulonglong2 b[4];
#pragma unroll
            for (int nn = 0; nn < 4; nn++)
                b[nn] = *(const ulonglong2*)&Bs[tn * 4 + nn][4 * j];
#pragma unroll
            for (int mm = 0; mm < 8; mm++) {
                ulonglong2 a = *(const ulonglong2*)&As[tm * 8 + mm][4 * j];
#pragma unroll
                for (int nn = 0; nn < 4; nn++) {
                    acc[mm][nn] = fma2(a.x, b[nn].x, acc[mm][nn]);
                    acc[mm][nn] = fma2(a.y, b[nn].y, acc[mm][nn]);
                }
            }
        }
        __syncthreads();
    }

#pragma unroll
    for (int nn = 0; nn < 4; nn++) {
        int n = n0 + tn * 4 + nn;
        if (n >= H_) continue;
        float bias = bh[n];
#pragma unroll
        for (int mm = 0; mm < 8; mm++) {
            int m = m0 + tm * 8 + mm;
            float2 f = u2f2(acc[mm][nn]);
            out[(size_t)m * H_ + n] = f.x + f.y + bias;
        }
    }
}

// ---------------------------------------------------------------------------
// Kernel 2: recurrence, register-tiled outer product.
//   CTA = 8 batches (64 CTAs), 256 threads. thread t: rg = t>>2 (row group,
//   rows 4*rg..4*rg+3), ks = t&3 (k slice). Each thread accumulates
//   acc[4 rows][4 batch-pairs] (f32x2 packs the batch pair) over its k slice:
//     main k: ks*55 + j, j<55  (weights in smem, row stride 221 = bank-clean
//             for the (rg,ks) lane layout)
//     tail k: 220 + ks*8 + i, i<8  (weights in registers; k>=250 zero-pad)
//   hp2[k][b] layout (8 floats/row): one k row feeds 16 fma2 via 2 LDS.128.
//   Partials reduced over ks via shfl.bfly(1,2); ks==0 lanes finalize:
//   tanh, store to out, rewrite hp2 row (2 STS.128). 2 barriers/step.
// ---------------------------------------------------------------------------
#define WROWS 252
#define WST4  221
#define MAINK 220
#define KPJ   55
#define TAILK 8
#define BT8   8

__global__ __launch_bounds__(256, 1) void rnn_rec4(
    const float* __restrict__ h0, const float* __restrict__ Wh,
    float* __restrict__ out)
{
    extern __shared__ float sm[];
    float* Wsm = sm;                       // 252 * 221
    float* hp2 = sm + WROWS * WST4;        // 252 * 8

    const int t  = threadIdx.x;
    const int rg = t >> 2;                 // 0..63
    const int ks = t & 3;
    const int b0 = blockIdx.x * BT8;

    // weights k<220 into smem (rows >= 250 zero)
    for (int idx = t; idx < WROWS * MAINK; idx += 256) {
        int r = idx / MAINK;
        int k = idx - r * MAINK;
        Wsm[r * WST4 + k] = (r < H_) ? Wh[(size_t)r * H_ + k] : 0.f;
    }
    // tail weights k in [220,252) (zero beyond 249 / row>=250)
    float tw[4][TAILK];
#pragma unroll
    for (int rr = 0; rr < 4; rr++) {
        int r = rg * 4 + rr;
#pragma unroll
        for (int i = 0; i < TAILK; i++) {
            int k = MAINK + ks * TAILK + i;
            tw[rr][i] = (r < H_ && k < H_) ? Wh[(size_t)r * H_ + k] : 0.f;
        }
    }
    // hp2 init: hp2[k*8 + b] = h0[b0+b][k]  (k rows 250,251 zero, stay zero)
    for (int idx = t; idx < WROWS * 8; idx += 256) {
        int k = idx >> 3;
        int b = idx & 7;
        hp2[idx] = (k < H_) ? h0[(size_t)(b0 + b) * H_ + k] : 0.f;
    }
    __syncthreads();

    const float* wbase = Wsm + (rg * 4) * WST4;

    for (int ts = 0; ts < T_; ts++) {
        // xp prefetch: only finalizing lanes need it
        float xpv[4][BT8];
        if (ks == 0) {
#pragma unroll
            for (int rr = 0; rr < 4; rr++) {
                int r = rg * 4 + rr;
                if (r < H_) {
#pragma unroll
                    for (int b = 0; b < BT8; b++)
                        xpv[rr][b] = out[((size_t)(b0 + b) * T_ + ts) * H_ + r];
                }
            }
        }

        unsigned long long acc[4][4];
#pragma unroll
        for (int rr = 0; rr < 4; rr++)
#pragma unroll
            for (int bp = 0; bp < 4; bp++) acc[rr][bp] = 0ull;

        // main k slice: k = ks*55 + j
        const int kbase = ks * KPJ;
#pragma unroll 5
        for (int j = 0; j < KPJ; j++) {
            const int k = kbase + j;
            ulonglong2 hA = *(const ulonglong2*)(hp2 + k * 8);      // b0..3
            ulonglong2 hB = *(const ulonglong2*)(hp2 + k * 8 + 4);  // b4..7
#pragma unroll
            for (int rr = 0; rr < 4; rr++) {
                float w = wbase[rr * WST4 + k];
                unsigned long long w2 = f2u2(w, w);
                acc[rr][0] = fma2(w2, hA.x, acc[rr][0]);
                acc[rr][1] = fma2(w2, hA.y, acc[rr][1]);
                acc[rr][2] = fma2(w2, hB.x, acc[rr][2]);
                acc[rr][3] = fma2(w2, hB.y, acc[rr][3]);
            }
        }
        // tail k: k = 220 + ks*8 + i (weights in regs)
#pragma unroll
        for (int i = 0; i < TAILK; i++) {
            const int k = MAINK + ks * TAILK + i;
            ulonglong2 hA = *(const ulonglong2*)(hp2 + k * 8);
            ulonglong2 hB = *(const ulonglong2*)(hp2 + k * 8 + 4);
#pragma unroll
            for (int rr = 0; rr < 4; rr++) {
                unsigned long long w2 = f2u2(tw[rr][i], tw[rr][i]);
                acc[rr][0] = fma2(w2, hA.x, acc[rr][0]);
                acc[rr][1] = fma2(w2, hA.y, acc[rr][1]);
                acc[rr][2] = fma2(w2, hB.x, acc[rr][2]);
                acc[rr][3] = fma2(w2, hB.y, acc[rr][3]);
            }
        }

        // reduce over the 4 k-slices (lane quads; all 256 threads participate)
#pragma unroll
        for (int rr = 0; rr < 4; rr++)
#pragma unroll
            for (int bp = 0; bp < 4; bp++) {
                unsigned long long o =
                    __shfl_xor_sync(0xffffffffu, acc[rr][bp], 1);
                acc[rr][bp] = add2(acc[rr][bp], o);
                o = __shfl_xor_sync(0xffffffffu, acc[rr][bp], 2);
                acc[rr][bp] = add2(acc[rr][bp], o);
            }

        __syncthreads();   // all hp2 reads of this step complete

        if (ks == 0) {
#pragma unroll
            for (int rr = 0; rr < 4; rr++) {
                int r = rg * 4 + rr;
                if (r < H_) {
                    float res[BT8];
#pragma unroll
                    for (int bp = 0; bp < 4; bp++) {
                        float2 f = u2f2(acc[rr][bp]);
                        res[2 * bp]     = tanhf(xpv[rr][2 * bp] + f.x);
                        res[2 * bp + 1] = tanhf(xpv[rr][2 * bp + 1] + f.y);
                    }
#pragma unroll
                    for (int b = 0; b < BT8; b++)
                        out[((size_t)(b0 + b) * T_ + ts) * H_ + r] = res[b];
                    *(float4*)(hp2 + r * 8) =
                        make_float4(res[0], res[1], res[2], res[3]);
                    *(float4*)(hp2 + r * 8 + 4) =
                        make_float4(res[4], res[5], res[6], res[7]);
                }
            }
        }
        __syncthreads();   // hp2 writes visible before next step's reads
    }
}

// ---------------------------------------------------------------------------
extern "C" void kernel_launch(void* const* d_in, const int* in_sizes, int n_in,
                              void* d_out, int out_size)
{
    const float* x  = (const float*)d_in[0];
    const float* h0 = (const float*)d_in[1];
    const float* Wx = (const float*)d_in[2];
    const float* Wh = (const float*)d_in[3];
    const float* bh = (const float*)d_in[4];
    float* out = (float*)d_out;

    static int attr_done = 0;
    size_t smem2 = (size_t)(WROWS * WST4 + WROWS * 8) * sizeof(float);
    if (!attr_done) {
        cudaFuncSetAttribute(rnn_rec4,
                             cudaFuncAttributeMaxDynamicSharedMemorySize,
                             (int)smem2);
        attr_done = 1;
    }

    // 1) xproj + bias into d_out (scratch reuse, no allocation)
    dim3 g1((B_ * T_) / BM, (H_ + BN - 1) / BN);
    xproj_kernel<<<g1, 256>>>(x, Wx, bh, out);

    // 2) recurrence, in-place on d_out: 64 CTAs x 256 threads
    rnn_rec4<<<B_ / BT8, 256, smem2>>>(h0, Wh, out);
}

// round 13
// speedup vs baseline: 2.2347x; 1.7968x over previous
#include <cuda_runtime.h>
#include <math.h>
#include <string.h>

#define B_ 512
#define T_ 512
#define I_ 256
#define H_ 250

// ---------------------------------------------------------------------------
// packed fp32x2 helpers
// ---------------------------------------------------------------------------
__device__ __forceinline__ unsigned long long fma2(unsigned long long a,
                                                   unsigned long long b,
                                                   unsigned long long c) {
    unsigned long long d;
    asm("fma.rn.f32x2 %0, %1, %2, %3;" : "=l"(d) : "l"(a), "l"(b), "l"(c));
    return d;
}
__device__ __forceinline__ unsigned long long add2(unsigned long long a,
                                                   unsigned long long b) {
    unsigned long long d;
    asm("add.rn.f32x2 %0, %1, %2;" : "=l"(d) : "l"(a), "l"(b));
    return d;
}
__device__ __forceinline__ float2 u2f2(unsigned long long u) {
    float2 f; memcpy(&f, &u, 8); return f;
}
__device__ __forceinline__ unsigned long long f2u2(float x, float y) {
    unsigned long long u;
    asm("mov.b64 %0, {%1, %2};" : "=l"(u) : "f"(x), "f"(y));
    return u;
}

// ---------------------------------------------------------------------------
// Kernel 1: xproj GEMM (unchanged — measured at ~97% of scalar fma2 peak)
// ---------------------------------------------------------------------------
#define BM 128
#define BN 64
#define BK 32
#define TSTRA 36

__global__ __launch_bounds__(256, 2) void xproj_kernel(
    const float* __restrict__ x, const float* __restrict__ Wx,
    const float* __restrict__ bh, float* __restrict__ out)
{
    __shared__ float As[BM][TSTRA];
    __shared__ float Bs[BN][TSTRA];

    const int m0  = blockIdx.x * BM;
    const int n0  = blockIdx.y * BN;
    const int tid = threadIdx.x;
    const int tn  = tid & 15;
    const int tm  = tid >> 4;

    unsigned long long acc[8][4];
#pragma unroll
    for (int i = 0; i < 8; i++)
#pragma unroll
        for (int j = 0; j < 4; j++) acc[i][j] = 0ull;

    const int ar = tid >> 3;
    const int ac = (tid & 7) * 4;

    for (int k0 = 0; k0 < I_; k0 += BK) {
#pragma unroll
        for (int p = 0; p < 4; p++) {
            int row = p * 32 + ar;
            float4 v = *(const float4*)(x + (size_t)(m0 + row) * I_ + k0 + ac);
            *(float4*)&As[row][ac] = v;
        }
#pragma unroll
        for (int p = 0; p < 2; p++) {
            int row = p * 32 + ar;
            int n = n0 + row;
            float4 v = make_float4(0.f, 0.f, 0.f, 0.f);
            if (n < H_) v = *(const float4*)(Wx + (size_t)n * I_ + k0 + ac);
            *(float4*)&Bs[row][ac] = v;
        }
        __syncthreads();

#pragma unroll
        for (int j = 0; j < BK / 4; j++) {
            ulonglong2 b[4];
#pragma unroll
            for (int nn = 0; nn < 4; nn++)
                b[nn] = *(const ulonglong2*)&Bs[tn * 4 + nn][4 * j];
#pragma unroll
            for (int mm = 0; mm < 8; mm++) {
                ulonglong2 a = *(const ulonglong2*)&As[tm * 8 + mm][4 * j];
#pragma unroll
                for (int nn = 0; nn < 4; nn++) {
                    acc[mm][nn] = fma2(a.x, b[nn].x, acc[mm][nn]);
                    acc[mm][nn] = fma2(a.y, b[nn].y, acc[mm][nn]);
                }
            }
        }
        __syncthreads();
    }

#pragma unroll
    for (int nn = 0; nn < 4; nn++) {
        int n = n0 + tn * 4 + nn;
        if (n >= H_) continue;
        float bias = bh[n];
#pragma unroll
        for (int mm = 0; mm < 8; mm++) {
            int m = m0 + tm * 8 + mm;
            float2 f = u2f2(acc[mm][nn]);
            out[(size_t)m * H_ + n] = f.x + f.y + bias;
        }
    }
}

// ---------------------------------------------------------------------------
// Kernel 2: recurrence rec5 (round-12 design, hp buffer now 16B-aligned).
//   128 CTAs x 256 threads, CTA = 4 batches.
//   thread (rg = t>>3, ks = t&7): 8 rows (8*rg..8*rg+7), k slice {k==ks mod 8}.
//   Main k<224 from smem (row stride 227; 8-rows x 8-ks LDS.32 pattern hits
//   all 32 banks); tail k in [224,256) from 32 regs (zeros past 249).
//   hp[k][4b] rows: one LDS.128 (quad-broadcast dedup) feeds 16 fma2.
//   Reduce-scatter over ks (select-window, 3 shfl stages) leaves each lane
//   its own row's full sum in static registers; lane finalizes row 8*rg+ks:
//   4 tanh + 4 coalesced STG + 1 STS.128. Two barriers/step.
// ---------------------------------------------------------------------------
#define WST5  227
#define MK5   224
#define HPK5  256
#define HPOFF 56752   // H_*WST5 = 56750, padded to 16B boundary (56752*4 % 16 == 0)

__global__ __launch_bounds__(256, 1) void rnn_rec5(
    const float* __restrict__ h0, const float* __restrict__ Wh,
    float* __restrict__ out)
{
    extern __shared__ float sm[];
    float* Wsm = sm;                    // 250 * 227 floats (+2 pad)
    float* hp  = sm + HPOFF;            // 256 * 4 floats, 16B-aligned

    const int t  = threadIdx.x;
    const int rg = t >> 3;              // 0..31
    const int ks = t & 7;
    const int b0 = blockIdx.x * 4;

    // weights k<224 into smem
    for (int idx = t; idx < H_ * MK5; idx += 256) {
        int r = idx / MK5, k = idx - r * MK5;
        Wsm[r * WST5 + k] = Wh[(size_t)r * H_ + k];
    }
    // tail weights k in [224,256): k = 224 + 8i + ks
    float tw[8][4];
#pragma unroll
    for (int rr = 0; rr < 8; rr++) {
        int r = rg * 8 + rr;
#pragma unroll
        for (int i = 0; i < 4; i++) {
            int k = MK5 + 8 * i + ks;
            tw[rr][i] = (r < H_ && k < H_) ? Wh[(size_t)r * H_ + k] : 0.f;
        }
    }
    // hp init: hp[k*4 + b]; k >= 250 zero (never rewritten, tail weights zero)
    for (int idx = t; idx < HPK5 * 4; idx += 256) {
        int k = idx >> 2, b = idx & 3;
        hp[idx] = (k < H_) ? h0[(size_t)(b0 + b) * H_ + k] : 0.f;
    }
    __syncthreads();

    // per-row weight base pointers (+ks folded in: literal offset = 8j floats)
    const float* wr[8];
#pragma unroll
    for (int rr = 0; rr < 8; rr++) {
        int r = rg * 8 + rr; if (r > H_ - 1) r = H_ - 1;   // dummy rows -> 249
        wr[rr] = Wsm + r * WST5 + ks;
    }
    const float* hpp = hp + ks * 4;     // 16B-aligned (hp aligned, ks*16B)
    const int  rfin = rg * 8 + ks;
    const bool fact = (rfin < H_);

    for (int ts = 0; ts < T_; ts++) {
        // prefetch xproj values (coalesced: warp covers 32 consecutive rows)
        float xp[4];
        if (fact) {
#pragma unroll
            for (int b = 0; b < 4; b++)
                xp[b] = out[((size_t)(b0 + b) * T_ + ts) * H_ + rfin];
        }

        unsigned long long acc[8][2];
#pragma unroll
        for (int rr = 0; rr < 8; rr++) { acc[rr][0] = 0ull; acc[rr][1] = 0ull; }

        // main: k = 8j + ks, j < 28  (full unroll -> literal LDS offsets)
#pragma unroll
        for (int j = 0; j < MK5 / 8; j++) {
            ulonglong2 h2 = *(const ulonglong2*)(hpp + 32 * j);
#pragma unroll
            for (int rr = 0; rr < 8; rr++) {
                float w = wr[rr][8 * j];
                unsigned long long w2 = f2u2(w, w);
                acc[rr][0] = fma2(w2, h2.x, acc[rr][0]);
                acc[rr][1] = fma2(w2, h2.y, acc[rr][1]);
            }
        }
        // tail: k = 224 + 8i + ks (weights in regs, zero past 249)
#pragma unroll
        for (int i = 0; i < 4; i++) {
            ulonglong2 h2 = *(const ulonglong2*)(hpp + (MK5 + 8 * i) * 4);
#pragma unroll
            for (int rr = 0; rr < 8; rr++) {
                unsigned long long w2 = f2u2(tw[rr][i], tw[rr][i]);
                acc[rr][0] = fma2(w2, h2.x, acc[rr][0]);
                acc[rr][1] = fma2(w2, h2.y, acc[rr][1]);
            }
        }

        // reduce-scatter over ks bits {4,2,1}: lane ends with row (8rg+ks)
        // full sum in fin[] (static registers)
        unsigned long long fin[2];
#pragma unroll
        for (int p = 0; p < 2; p++) {
            unsigned long long w1[4], w2r[2];
#pragma unroll
            for (int i = 0; i < 4; i++) {
                unsigned long long snd = (ks & 4) ? acc[i][p] : acc[i + 4][p];
                unsigned long long rcv = __shfl_xor_sync(0xffffffffu, snd, 4);
                unsigned long long kp  = (ks & 4) ? acc[i + 4][p] : acc[i][p];
                w1[i] = add2(kp, rcv);
            }
#pragma unroll
            for (int i = 0; i < 2; i++) {
                unsigned long long snd = (ks & 2) ? w1[i] : w1[i + 2];
                unsigned long long rcv = __shfl_xor_sync(0xffffffffu, snd, 2);
                unsigned long long kp  = (ks & 2) ? w1[i + 2] : w1[i];
                w2r[i] = add2(kp, rcv);
            }
            {
                unsigned long long snd = (ks & 1) ? w2r[0] : w2r[1];
                unsigned long long rcv = __shfl_xor_sync(0xffffffffu, snd, 1);
                unsigned long long kp  = (ks & 1) ? w2r[1] : w2r[0];
                fin[p] = add2(kp, rcv);
            }
        }

        __syncthreads();   // all hp reads of this step complete

        if (fact) {
            float2 fA = u2f2(fin[0]), fB = u2f2(fin[1]);
            float v0 = tanhf(xp[0] + fA.x);
            float v1 = tanhf(xp[1] + fA.y);
            float v2 = tanhf(xp[2] + fB.x);
            float v3 = tanhf(xp[3] + fB.y);
            out[((size_t)(b0 + 0) * T_ + ts) * H_ + rfin] = v0;
            out[((size_t)(b0 + 1) * T_ + ts) * H_ + rfin] = v1;
            out[((size_t)(b0 + 2) * T_ + ts) * H_ + rfin] = v2;
            out[((size_t)(b0 + 3) * T_ + ts) * H_ + rfin] = v3;
            *(float4*)(hp + rfin * 4) = make_float4(v0, v1, v2, v3);
        }
        __syncthreads();   // hp writes visible before next step's reads
    }
}

// ---------------------------------------------------------------------------
extern "C" void kernel_launch(void* const* d_in, const int* in_sizes, int n_in,
                              void* d_out, int out_size)
{
    const float* x  = (const float*)d_in[0];
    const float* h0 = (const float*)d_in[1];
    const float* Wx = (const float*)d_in[2];
    const float* Wh = (const float*)d_in[3];
    const float* bh = (const float*)d_in[4];
    float* out = (float*)d_out;

    static int attr_done = 0;
    size_t smem2 = (size_t)(HPOFF + HPK5 * 4) * sizeof(float);
    if (!attr_done) {
        cudaFuncSetAttribute(rnn_rec5,
                             cudaFuncAttributeMaxDynamicSharedMemorySize,
                             (int)smem2);
        attr_done = 1;
    }

    // 1) xproj + bias into d_out (scratch reuse)
    dim3 g1((B_ * T_) / BM, (H_ + BN - 1) / BN);
    xproj_kernel<<<g1, 256>>>(x, Wx, bh, out);

    // 2) recurrence: 128 CTAs x 256 threads, in-place on d_out
    rnn_rec5<<<B_ / 4, 256, smem2>>>(h0, Wh, out);
}